// round 6
// baseline (speedup 1.0000x reference)
#include <cuda_runtime.h>
#include <math.h>

// ---------------------------------------------------------------------------
// expression[c,g] = bias1[gene_ix[g]] + sum_{frags in bucket c*gene_n+g}
//                   dot(sin(coords[f,:,None]*freq+shift).reshape(40), w)
// Linearity -> per-fragment scalar g0(x)+g1(y): two fixed 1-D LUTs + lerp.
// Sorted bucket ids -> 4 frags/lane branchless run combine, one warp
// segmented scan per 128-frag window, predicated RED per distinct bucket.
// R6: 4 independent windows per warp iteration for ILP / latency hiding.
// ---------------------------------------------------------------------------

#define TAB   256
#define T_LO  (-9.0f)
#define T_HI  ( 9.0f)
#define FULL  0xffffffffu
#define NWIN  4

__device__ float2 g_tbl[2][TAB];     // (value, slope-to-next)

// ---------------------------------------------------------------------------
// prep: first TBL_BLOCKS blocks build the LUT (warp per point, lane per freq
// term); remaining blocks init out with the permuted bias row via smem.
// ---------------------------------------------------------------------------
#define TBL_POINTS  (2 * TAB)
#define TBL_BLOCKS  ((TBL_POINTS * 32 + 255) / 256)
#define INIT_ROWS   8
#define MAX_GENE    4096

__global__ void prep_kernel(const float* __restrict__ freqs,
                            const float* __restrict__ shifts,
                            const float* __restrict__ w,
                            const float* __restrict__ bias,
                            const int*   __restrict__ gene_ix,
                            float*       __restrict__ out,
                            int gene_n, int total)
{
    if (blockIdx.x < TBL_BLOCKS) {
        int gw   = blockIdx.x * (blockDim.x >> 5) + (threadIdx.x >> 5);
        int lane = threadIdx.x & 31;
        if (gw < TBL_POINTS) {
            int which = gw / TAB;
            int k     = gw % TAB;
            const float step = (T_HI - T_LO) / (float)TAB;
            float x0 = T_LO + (float)k * step;
            float x1 = x0 + step;
            float v0 = 0.f, v1 = 0.f;
            if (lane < 20) {
                float f = freqs[lane], s = shifts[lane], c = w[which * 20 + lane];
                v0 = c * sinf(fmaf(x0, f, s));
                v1 = c * sinf(fmaf(x1, f, s));
            }
            #pragma unroll
            for (int off = 16; off; off >>= 1) {
                v0 += __shfl_down_sync(FULL, v0, off);
                v1 += __shfl_down_sync(FULL, v1, off);
            }
            if (lane == 0) g_tbl[which][k] = make_float2(v0, v1 - v0);
        }
        return;
    }

    int ib = blockIdx.x - TBL_BLOCKS;

    if ((gene_n & 3) == 0 && gene_n <= MAX_GENE && total % gene_n == 0) {
        __shared__ float pb[MAX_GENE];
        for (int g = threadIdx.x; g < gene_n; g += blockDim.x)
            pb[g] = __ldg(&bias[__ldg(&gene_ix[g])]);
        __syncthreads();

        const float4* pb4 = reinterpret_cast<const float4*>(pb);
        float4*       o4  = reinterpret_cast<float4*>(out);
        int row_q  = gene_n >> 2;
        int rows   = total / gene_n;
        int r0     = ib * INIT_ROWS;
        int nq     = min(INIT_ROWS, rows - r0) * row_q;
        if (nq <= 0) return;
        long base4 = (long)r0 * row_q;
        for (int t = threadIdx.x; t < nq; t += blockDim.x)
            o4[base4 + t] = pb4[t % row_q];
    } else {
        for (long i = (long)ib * blockDim.x * INIT_ROWS * 4 + threadIdx.x;
             i < (long)total && i < (long)(ib + 1) * blockDim.x * INIT_ROWS * 4;
             i += blockDim.x)
            out[i] = __ldg(&bias[__ldg(&gene_ix[(int)(i % gene_n)])]);
    }
}

// ---------------------------------------------------------------------------

__device__ __forceinline__ float lerp1(const float2* __restrict__ s, float x)
{
    const float scale = (float)TAB / (T_HI - T_LO);
    const float offs  = -T_LO * scale;
    const float hi    = (float)TAB - 0.001f;
    float u = fminf(fmaxf(fmaf(x, scale, offs), 0.f), hi);
    int   k = (int)u;
    float fr = u - (float)k;
    float2 t = s[k];
    return fmaf(fr, t.y, t.x);
}

__global__ void __launch_bounds__(256)
frag_kernel(const float4* __restrict__ coords2,   // 2 frags per element
            const int4*   __restrict__ ix4,       // 4 bucket ids per element
            const float*  __restrict__ coords_raw,
            const int*    __restrict__ ix_raw,
            float*        __restrict__ out,
            int nquads, int F)
{
    __shared__ float2 s0[TAB];
    __shared__ float2 s1[TAB];
    {
        const float2* src = &g_tbl[0][0];
        for (int i = threadIdx.x; i < 2 * TAB; i += blockDim.x) {
            if (i < TAB) s0[i] = src[i];
            else         s1[i - TAB] = src[i];
        }
    }
    __syncthreads();

    // Leftover fragments (F % 4): one thread.
    if (blockIdx.x == 0 && threadIdx.x == 0) {
        for (int f = 4 * nquads; f < F; ++f) {
            float x = coords_raw[2 * f], y = coords_raw[2 * f + 1];
            atomicAdd(out + ix_raw[f], lerp1(s0, x) + lerp1(s1, y));
        }
    }

    int lane   = threadIdx.x & 31;
    int gwarp  = (blockIdx.x * blockDim.x + threadIdx.x) >> 5;
    int nwarps = (gridDim.x * blockDim.x) >> 5;

    // Each iteration: NWIN consecutive 32-quad windows, fully independent
    // dataflow -> compiler interleaves the scan/lerp chains (ILP).
    for (long wbase = (long)gwarp * (32 * NWIN); wbase < (long)nquads;
         wbase += (long)nwarps * (32 * NWIN)) {

        // ---- load phase: all global loads issued up front (MLP) ----
        float4 cA[NWIN], cB[NWIN];
        int4   b[NWIN];
        bool   val[NWIN];
        #pragma unroll
        for (int j = 0; j < NWIN; ++j) {
            long q = wbase + 32 * j + lane;
            val[j] = q < (long)nquads;
            if (val[j]) {
                cA[j] = __ldcs(&coords2[2 * q]);
                cB[j] = __ldcs(&coords2[2 * q + 1]);
                b[j]  = __ldcs(&ix4[q]);
            } else {
                cA[j] = make_float4(0,0,0,0);
                cB[j] = make_float4(0,0,0,0);
                b[j]  = make_int4(-1,-1,-1,-1);
            }
        }

        // ---- compute phase: NWIN independent window pipelines ----
        #pragma unroll
        for (int j = 0; j < NWIN; ++j) {
            float v0 = lerp1(s0, cA[j].x) + lerp1(s1, cA[j].y);
            float v1 = lerp1(s0, cA[j].z) + lerp1(s1, cA[j].w);
            float v2 = lerp1(s0, cB[j].x) + lerp1(s1, cB[j].y);
            float v3 = lerp1(s0, cB[j].z) + lerp1(s1, cB[j].w);

            bool e01 = (b[j].x == b[j].y);
            bool e12 = (b[j].y == b[j].z);
            bool e23 = (b[j].z == b[j].w);
            float c0 = v0;
            float c1 = v1 + (e01 ? c0 : 0.f);
            float c2 = v2 + (e12 ? c1 : 0.f);
            float c3 = v3 + (e23 ? c2 : 0.f);
            bool same = e01 && e12 && e23;
            float hsum = !e01 ? c0 : (!e12 ? c1 : c2);

            int  st_prev = __shfl_up_sync(FULL, b[j].w, 1);
            bool cont    = (lane > 0) && same && (st_prev == b[j].w);

            unsigned hb    = __ballot_sync(FULL, !cont);
            unsigned below = hb & (0xffffffffu >> (31 - lane));
            int seg = 31 - __clz(below);

            float S = c3;
            #pragma unroll
            for (int off = 1; off < 32; off <<= 1) {
                float n = __shfl_up_sync(FULL, S, off);
                if (lane - off >= seg) S += n;
            }

            float Sprev = __shfl_up_sync(FULL, S, 1);
            int   nb0   = __shfl_down_sync(FULL, b[j].x, 1);
            bool consumed = (lane < 31) && (nb0 == b[j].w);

            bool f_int1 = val[j] && !e12 && !e01;
            bool f_int2 = val[j] && !e23 && !(e01 && e12);
            bool f_head = val[j] && !same;
            bool f_tail = val[j] && !consumed;
            float hv = hsum + ((lane > 0 && st_prev == b[j].x) ? Sprev : 0.f);

            if (f_int1) atomicAdd(out + b[j].y, c1);
            if (f_int2) atomicAdd(out + b[j].z, c2);
            if (f_head) atomicAdd(out + b[j].x, hv);
            if (f_tail) atomicAdd(out + b[j].w, S);
        }
    }
}

// ---------------------------------------------------------------------------

extern "C" void kernel_launch(void* const* d_in, const int* in_sizes, int n_in,
                              void* d_out, int out_size)
{
    // 0 coords, 1 cellxgene_ix, 2 cell_n, 3 gene_n, 4 gene_ix,
    // 5 frequencies, 6 shifts, 7 weight1, 8 bias1
    int off = (n_in >= 9) ? 0 : -2;

    const float* coords  = (const float*)d_in[0];
    const int*   ix      = (const int*)  d_in[1];
    const int*   gene_ix = (const int*)  d_in[4 + off];
    const float* freqs   = (const float*)d_in[5 + off];
    const float* shifts  = (const float*)d_in[6 + off];
    const float* w       = (const float*)d_in[7 + off];
    const float* bias    = (const float*)d_in[8 + off];

    int F      = in_sizes[0] / 2;
    int gene_n = in_sizes[4 + off];
    float* out = (float*)d_out;

    int init_blocks;
    if ((gene_n & 3) == 0 && gene_n <= MAX_GENE && out_size % gene_n == 0) {
        int rows = out_size / gene_n;
        init_blocks = (rows + INIT_ROWS - 1) / INIT_ROWS;
    } else {
        init_blocks = (out_size + 256 * INIT_ROWS * 4 - 1) / (256 * INIT_ROWS * 4);
    }
    prep_kernel<<<TBL_BLOCKS + init_blocks, 256>>>(freqs, shifts, w, bias,
                                                   gene_ix, out, gene_n, out_size);

    int nquads = F / 4;
    frag_kernel<<<1184, 256>>>((const float4*)coords, (const int4*)ix,
                               coords, ix, out, nquads, F);
}

// round 7
// speedup vs baseline: 1.1067x; 1.1067x over previous
#include <cuda_runtime.h>
#include <math.h>

// ---------------------------------------------------------------------------
// expression[c,g] = bias1[gene_ix[g]] + sum_{frags in bucket c*gene_n+g}
//                   dot(sin(coords[f,:,None]*freq+shift).reshape(40), w)
// Per-fragment scalar g0(x)+g1(y): two fixed 1-D LUTs + lerp.
// Sorted buckets -> 4 frags/lane branchless run combine, truncated depth-2
// segmented scan with modulo-4 flush (exact for any run length),
// predicated RED per distinct bucket. ix prefetched one iteration ahead.
// ---------------------------------------------------------------------------

#define TAB   256
#define T_LO  (-9.0f)
#define T_HI  ( 9.0f)
#define FULL  0xffffffffu

__device__ float2 g_tbl[2][TAB];     // (value, slope-to-next)

// ---------------------------------------------------------------------------
#define TBL_POINTS  (2 * TAB)
#define TBL_BLOCKS  ((TBL_POINTS * 32 + 255) / 256)
#define INIT_ROWS   2
#define MAX_GENE    4096

__global__ void prep_kernel(const float* __restrict__ freqs,
                            const float* __restrict__ shifts,
                            const float* __restrict__ w,
                            const float* __restrict__ bias,
                            const int*   __restrict__ gene_ix,
                            float*       __restrict__ out,
                            int gene_n, int total)
{
    if (blockIdx.x < TBL_BLOCKS) {
        int gw   = blockIdx.x * (blockDim.x >> 5) + (threadIdx.x >> 5);
        int lane = threadIdx.x & 31;
        if (gw < TBL_POINTS) {
            int which = gw / TAB;
            int k     = gw % TAB;
            const float step = (T_HI - T_LO) / (float)TAB;
            float x0 = T_LO + (float)k * step;
            float x1 = x0 + step;
            float v0 = 0.f, v1 = 0.f;
            if (lane < 20) {
                float f = freqs[lane], s = shifts[lane], c = w[which * 20 + lane];
                v0 = c * sinf(fmaf(x0, f, s));
                v1 = c * sinf(fmaf(x1, f, s));
            }
            #pragma unroll
            for (int off = 16; off; off >>= 1) {
                v0 += __shfl_down_sync(FULL, v0, off);
                v1 += __shfl_down_sync(FULL, v1, off);
            }
            if (lane == 0) g_tbl[which][k] = make_float2(v0, v1 - v0);
        }
        return;
    }

    int ib = blockIdx.x - TBL_BLOCKS;

    if ((gene_n & 3) == 0 && gene_n <= MAX_GENE && total % gene_n == 0) {
        __shared__ float pb[MAX_GENE];
        for (int g = threadIdx.x; g < gene_n; g += blockDim.x)
            pb[g] = __ldg(&bias[__ldg(&gene_ix[g])]);
        __syncthreads();

        const float4* pb4 = reinterpret_cast<const float4*>(pb);
        float4*       o4  = reinterpret_cast<float4*>(out);
        int row_q  = gene_n >> 2;
        int rows   = total / gene_n;
        int r0     = ib * INIT_ROWS;
        int nq     = min(INIT_ROWS, rows - r0) * row_q;
        if (nq <= 0) return;
        long base4 = (long)r0 * row_q;
        for (int t = threadIdx.x; t < nq; t += blockDim.x)
            o4[base4 + t] = pb4[t % row_q];
    } else {
        for (long i = (long)ib * blockDim.x * INIT_ROWS * 4 + threadIdx.x;
             i < (long)total && i < (long)(ib + 1) * blockDim.x * INIT_ROWS * 4;
             i += blockDim.x)
            out[i] = __ldg(&bias[__ldg(&gene_ix[(int)(i % gene_n)])]);
    }
}

// ---------------------------------------------------------------------------

__device__ __forceinline__ float lerp1(const float2* __restrict__ s, float x)
{
    const float scale = (float)TAB / (T_HI - T_LO);
    const float offs  = -T_LO * scale;
    const float hi    = (float)TAB - 0.001f;
    float u = fminf(fmaxf(fmaf(x, scale, offs), 0.f), hi);
    int   k = (int)u;
    float fr = u - (float)k;
    float2 t = s[k];
    return fmaf(fr, t.y, t.x);
}

__global__ void __launch_bounds__(256)
frag_kernel(const float4* __restrict__ coords2,   // 2 frags per element
            const int4*   __restrict__ ix4,       // 4 bucket ids per element
            const float*  __restrict__ coords_raw,
            const int*    __restrict__ ix_raw,
            float*        __restrict__ out,
            int nquads, int F)
{
    __shared__ float2 s0[TAB];
    __shared__ float2 s1[TAB];
    {
        const float2* src = &g_tbl[0][0];
        for (int i = threadIdx.x; i < 2 * TAB; i += blockDim.x) {
            if (i < TAB) s0[i] = src[i];
            else         s1[i - TAB] = src[i];
        }
    }
    __syncthreads();

    // Leftover fragments (F % 4): one thread.
    if (blockIdx.x == 0 && threadIdx.x == 0) {
        for (int f = 4 * nquads; f < F; ++f) {
            float x = coords_raw[2 * f], y = coords_raw[2 * f + 1];
            atomicAdd(out + ix_raw[f], lerp1(s0, x) + lerp1(s1, y));
        }
    }

    int  lane   = threadIdx.x & 31;
    int  gwarp  = (blockIdx.x * blockDim.x + threadIdx.x) >> 5;
    int  nwarps = (gridDim.x * blockDim.x) >> 5;
    long stride = (long)nwarps * 32;

    // Prefetch bucket ids for the first window.
    long q0   = (long)gwarp * 32 + lane;
    int4 bpre = (q0 < (long)nquads) ? __ldcs(&ix4[q0])
                                    : make_int4(-1, -1, -1, -1);

    for (long qbase = (long)gwarp * 32; qbase < (long)nquads; qbase += stride) {
        long q     = qbase + lane;
        bool valid = q < (long)nquads;

        float4 cA = make_float4(0,0,0,0), cB = make_float4(0,0,0,0);
        if (valid) {
            cA = __ldcs(&coords2[2 * q]);
            cB = __ldcs(&coords2[2 * q + 1]);
        }
        int4 b = bpre;

        // Prefetch next window's bucket ids.
        long qn = q + stride;
        bpre = (qn < (long)nquads) ? __ldcs(&ix4[qn])
                                   : make_int4(-1, -1, -1, -1);

        float v0 = lerp1(s0, cA.x) + lerp1(s1, cA.y);
        float v1 = lerp1(s0, cA.z) + lerp1(s1, cA.w);
        float v2 = lerp1(s0, cB.x) + lerp1(s1, cB.y);
        float v3 = lerp1(s0, cB.z) + lerp1(s1, cB.w);

        // Branchless cumulative run sums over the 4 sorted buckets.
        bool e01 = (b.x == b.y), e12 = (b.y == b.z), e23 = (b.z == b.w);
        float c0 = v0;
        float c1 = v1 + (e01 ? c0 : 0.f);
        float c2 = v2 + (e12 ? c1 : 0.f);
        float c3 = v3 + (e23 ? c2 : 0.f);
        bool  same = e01 && e12 && e23;
        float hsum = !e01 ? c0 : (!e12 ? c1 : c2);

        // Cross-lane: tail run (bucket b.w, sum c3).
        int  st_prev = __shfl_up_sync(FULL, b.w, 1);
        bool cont    = (lane > 0) && same && (st_prev == b.w);

        unsigned hb    = __ballot_sync(FULL, !cont);
        unsigned below = hb & (0xffffffffu >> (31 - lane));
        int seg = 31 - __clz(below);                 // bit 0 always set

        // Truncated depth-2 segmented scan: S covers lanes [max(seg,lane-3), lane].
        float S = c3;
        {
            float n1 = __shfl_up_sync(FULL, S, 1);
            if (lane - 1 >= seg) S += n1;
            float n2 = __shfl_up_sync(FULL, S, 2);
            if (lane - 2 >= seg) S += n2;
        }

        // Segment end = (next head above) - 1, else 31.
        unsigned above = (lane < 31) ? (hb & (0xFFFFFFFFu << (lane + 1))) : 0u;
        int nh1    = __ffs(above);                   // 1-based, 0 if none
        int segEnd = nh1 ? (nh1 - 2) : 31;

        float Sprev = __shfl_up_sync(FULL, S, 1);
        int   nb0   = __shfl_down_sync(FULL, b.x, 1);

        bool at_end   = (lane == segEnd);
        bool consumed = at_end && (lane < 31) && (nb0 == b.w);
        bool flushpos = (((segEnd - lane) & 3) == 0);

        bool f_int1 = valid && !e12 && !e01;
        bool f_int2 = valid && !e23 && !(e01 && e12);
        bool f_head = valid && !same;
        bool f_tail = valid && flushpos && !consumed;
        float hv = hsum + ((lane > 0 && st_prev == b.x) ? Sprev : 0.f);

        if (f_int1) atomicAdd(out + b.y, c1);
        if (f_int2) atomicAdd(out + b.z, c2);
        if (f_head) atomicAdd(out + b.x, hv);
        if (f_tail) atomicAdd(out + b.w, S);
    }
}

// ---------------------------------------------------------------------------

extern "C" void kernel_launch(void* const* d_in, const int* in_sizes, int n_in,
                              void* d_out, int out_size)
{
    // 0 coords, 1 cellxgene_ix, 2 cell_n, 3 gene_n, 4 gene_ix,
    // 5 frequencies, 6 shifts, 7 weight1, 8 bias1
    int off = (n_in >= 9) ? 0 : -2;

    const float* coords  = (const float*)d_in[0];
    const int*   ix      = (const int*)  d_in[1];
    const int*   gene_ix = (const int*)  d_in[4 + off];
    const float* freqs   = (const float*)d_in[5 + off];
    const float* shifts  = (const float*)d_in[6 + off];
    const float* w       = (const float*)d_in[7 + off];
    const float* bias    = (const float*)d_in[8 + off];

    int F      = in_sizes[0] / 2;
    int gene_n = in_sizes[4 + off];
    float* out = (float*)d_out;

    int init_blocks;
    if ((gene_n & 3) == 0 && gene_n <= MAX_GENE && out_size % gene_n == 0) {
        int rows = out_size / gene_n;
        init_blocks = (rows + INIT_ROWS - 1) / INIT_ROWS;
    } else {
        init_blocks = (out_size + 256 * INIT_ROWS * 4 - 1) / (256 * INIT_ROWS * 4);
    }
    prep_kernel<<<TBL_BLOCKS + init_blocks, 256>>>(freqs, shifts, w, bias,
                                                   gene_ix, out, gene_n, out_size);

    int nquads = F / 4;
    frag_kernel<<<1184, 256>>>((const float4*)coords, (const int4*)ix,
                               coords, ix, out, nquads, F);
}